// round 7
// baseline (speedup 1.0000x reference)
#include <cuda_runtime.h>

// ScaledDotProductAttention: B=4, W=64, H=64, C=256, M=32, D=32, T=8
// out[b,c,w,h] = sum_m v[b,w,h,c,m] * softmax_m( (q[b,w,h,m,:] . k[b,w,h,:]) / T )
//
// Pure HBM-streaming kernel (594 MB moved once).
// R2: fully coalesced 512B warp loads + shfl reductions.
// R3: 128-thread CTAs, HT=16, 1024 CTAs, occ 8, single wave (90.6 us, DRAM 85.8%).
// R4/R5 (reverted): occupancy/reg experiments regressed or neutral.
// R6: __stcs stores - neutral.
// R7: v streamed with 256-bit loads (ld.global.v8.f32, sm_100+ PTX 8.8):
//     1 KB contiguous per warp instruction, half the LDG count / L1tex
//     wavefront entries, 2-shfl reduction over 4-lane row groups.

#define C_DIM 256
#define M_DIM 32
#define D_DIM 32
#define W_DIM 64
#define H_DIM 64
#define HT 16          // h-tile per CTA

__global__ __launch_bounds__(128, 8)
void sdpa_kernel(const float* __restrict__ q,
                 const float* __restrict__ v,
                 const float* __restrict__ k,
                 float* __restrict__ out)
{
    __shared__ float wts[HT * M_DIM];        // [h_local][m] softmax weights, 2 KB
    __shared__ float res[C_DIM * (HT + 1)];  // [c][h_local], +1 pad, 17.4 KB

    const int hq = blockIdx.x;               // 0..3  (h-tile index)
    const int w  = blockIdx.y;               // 0..63
    const int b  = blockIdx.z;               // 0..3
    const int h0 = hq * HT;

    const int tid  = threadIdx.x;
    const int lane = tid & 31;
    const int wid  = tid >> 5;               // 0..3
    const int sub  = lane & 7;               // phase-1: position within 8-lane group
    const int grp  = lane >> 3;              // phase-1: which of 4 groups
    const int sub4 = lane & 3;               // phase-2: quarter-row within a c-row
    const int grp8 = lane >> 2;              // phase-2: which of 8 c-rows

    const long slice0 = ((long)(b * W_DIM + w) * H_DIM + h0);

    // ---------- Phase 1: softmax weights; warp wid owns slices wid*4 .. wid*4+3 ----------
    #pragma unroll
    for (int i = 0; i < 4; ++i) {
        const int  hl = wid * 4 + i;
        const long sl = slice0 + hl;

        const float4 k4 = *(const float4*)(k + sl * D_DIM + sub * 4);

        #pragma unroll
        for (int j = 0; j < 8; ++j) {
            const int m = j * 4 + grp;
            const float4 q4 = *(const float4*)(q + (sl * M_DIM + m) * D_DIM + sub * 4);
            float p = q4.x * k4.x + q4.y * k4.y + q4.z * k4.z + q4.w * k4.w;
            p += __shfl_xor_sync(0xffffffffu, p, 4);
            p += __shfl_xor_sync(0xffffffffu, p, 2);
            p += __shfl_xor_sync(0xffffffffu, p, 1);
            if (sub == 0) wts[hl * M_DIM + m] = p;   // raw logit
        }
        __syncwarp();

        const float logit = wts[hl * M_DIM + lane] * 0.125f;  // 1/TEMPERATURE
        float mx = logit;
        #pragma unroll
        for (int o = 16; o; o >>= 1) mx = fmaxf(mx, __shfl_xor_sync(0xffffffffu, mx, o));
        const float e = __expf(logit - mx);
        float s = e;
        #pragma unroll
        for (int o = 16; o; o >>= 1) s += __shfl_xor_sync(0xffffffffu, s, o);
        wts[hl * M_DIM + lane] = e / s;
    }
    __syncthreads();

    // ---------- Phase 2: stream v with 256-bit loads; warp owns 64 c-values ----------
    // Lane l covers v[sl][cbase + j*8 + (l>>2)][ (l&3)*8 .. +7 ]  -> warp = 1 KB contiguous.
    const int cbase = wid * 64;
    for (int hl = 0; hl < HT; ++hl) {
        // this lane's 8 weights (smem, conflict-free: 4-lane groups read distinct banks)
        const float4 wa = *(const float4*)(wts + hl * M_DIM + sub4 * 8);
        const float4 wb = *(const float4*)(wts + hl * M_DIM + sub4 * 8 + 4);
        const float* __restrict__ vbase = v + (slice0 + hl) * (long)(C_DIM * M_DIM);
        #pragma unroll
        for (int j = 0; j < 8; ++j) {
            const int c = cbase + j * 8 + grp8;
            const float* vp = vbase + c * M_DIM + sub4 * 8;
            float r0, r1, r2, r3, r4, r5, r6, r7;
            asm volatile("ld.global.v8.f32 {%0,%1,%2,%3,%4,%5,%6,%7}, [%8];"
                         : "=f"(r0), "=f"(r1), "=f"(r2), "=f"(r3),
                           "=f"(r4), "=f"(r5), "=f"(r6), "=f"(r7)
                         : "l"(vp));
            float p = r0 * wa.x + r1 * wa.y + r2 * wa.z + r3 * wa.w
                    + r4 * wb.x + r5 * wb.y + r6 * wb.z + r7 * wb.w;
            p += __shfl_xor_sync(0xffffffffu, p, 2);
            p += __shfl_xor_sync(0xffffffffu, p, 1);
            if (sub4 == 0) res[c * (HT + 1) + hl] = p;
        }
    }
    __syncthreads();

    // ---------- Phase 3: coalesced transposed writes: out[((b*C + c)*W + w)*H + h] ----------
    // 256*16 floats = 1024 float4; 128 threads -> 8 iterations. Streaming stores.
    #pragma unroll
    for (int it = 0; it < 8; ++it) {
        const int j  = it * 128 + tid;
        const int c2 = j >> 2;            // 0..255
        const int hb = (j & 3) << 2;      // 0,4,8,12
        const float* r = &res[c2 * (HT + 1) + hb];
        const float4 o4 = make_float4(r[0], r[1], r[2], r[3]);
        const long oidx = (((long)b * C_DIM + c2) * W_DIM + w) * H_DIM + (h0 + hb);
        __stcs((float4*)(out + oidx), o4);
    }
}

extern "C" void kernel_launch(void* const* d_in, const int* in_sizes, int n_in,
                              void* d_out, int out_size)
{
    // Resolve inputs by element count: q=16,777,216; v=134,217,728; k=524,288
    const float* q = nullptr;
    const float* v = nullptr;
    const float* k = nullptr;
    for (int i = 0; i < n_in; ++i) {
        if (in_sizes[i] == 16777216)       q = (const float*)d_in[i];
        else if (in_sizes[i] == 134217728) v = (const float*)d_in[i];
        else if (in_sizes[i] == 524288)    k = (const float*)d_in[i];
    }
    float* out = (float*)d_out;

    dim3 grid(H_DIM / HT, W_DIM, 4);   // (4, 64, 4) = 1024 CTAs
    sdpa_kernel<<<grid, 128>>>(q, v, k, out);
}